// round 6
// baseline (speedup 1.0000x reference)
#include <cuda_runtime.h>
#include <cuda_bf16.h>
#include <cstdint>

// Problem constants (fixed by the dataset problem)
#define NN   16384          // nodes
#define DD   128            // feature dim (in == out)
#define EE   524288         // edges
#define ROWCAP 192          // per-row slot cap (max expected degree ~57; Binomial(E,1/N))
#define GM_ROWS 32
#define NBLK_GEMM (NN / GM_ROWS)   // 512

// ---------------- device scratch (no allocations allowed) ----------------
__device__ float g_h[NN * DD];                 // 8 MB   h = x @ W
__device__ float g_s1[NN];
__device__ float g_s2[NN];
__device__ float g_Sh[DD];                     // total column sums (written by k_fill blk 0)
__device__ float g_ShPart[NBLK_GEMM][DD];      // per-gemm-block partial column sums
__device__ int   g_cnt[NN];                    // zero at start of every call (self-cleaning)
__device__ int   g_cols[NN * ROWCAP];          // slotted adjacency, 12.6 MB

// ---------------- GEMM: h = x @ W  (32 rows x 128 cols per block, f32x2 FMA)
//   Inner loop uses Blackwell packed fma.rn.f32x2: x pre-duplicated in smem as
//   float2{v,v}; W pairs read as 64-bit shared loads. 8 FFMA2 + 6 LDS.64 per k.
//   Epilogue: s1,s2 direct store; partial column sums -> g_ShPart.
__global__ void k_gemm(const float* __restrict__ x, const float* __restrict__ W,
                       const float* __restrict__ a) {
    __shared__ float  ws[64][128];   // 32 KB  [k][n] chunk
    __shared__ float2 xd[32][64];    // 16 KB  [m][k] chunk, each value duplicated

    const int tx = threadIdx.x & 31;        // 0..31 -> cols tx*4 .. tx*4+3
    const int ty = threadIdx.x >> 5;        // 0..7  -> rows ty*4 .. ty*4+3
    const int bm = blockIdx.x * GM_ROWS;

    unsigned long long accp[4][2];          // [row m][col pair] packed f32x2
    #pragma unroll
    for (int m = 0; m < 4; m++) { accp[m][0] = 0ull; accp[m][1] = 0ull; }

    for (int k0 = 0; k0 < DD; k0 += 64) {
        // load W chunk: 64x128 = 2048 float4, 8 per thread
        #pragma unroll
        for (int i = 0; i < 8; i++) {
            int idx = threadIdx.x + i * 256;
            int kk = idx >> 5, n4 = idx & 31;
            float4 v = ((const float4*)W)[(k0 + kk) * 32 + n4];
            *(float4*)&ws[kk][n4 * 4] = v;
        }
        // load x chunk, duplicated: 32 rows x 64 k = 512 float4, 2 per thread
        #pragma unroll
        for (int i = 0; i < 2; i++) {
            int idx = threadIdx.x + i * 256;
            int r = idx >> 4, c4 = idx & 15;
            float4 v = ((const float4*)x)[(bm + r) * 32 + (k0 >> 2) + c4];
            xd[r][c4 * 4 + 0] = make_float2(v.x, v.x);
            xd[r][c4 * 4 + 1] = make_float2(v.y, v.y);
            xd[r][c4 * 4 + 2] = make_float2(v.z, v.z);
            xd[r][c4 * 4 + 3] = make_float2(v.w, v.w);
        }
        __syncthreads();

        #pragma unroll 16
        for (int k = 0; k < 64; k++) {
            unsigned long long wp0 = *(const unsigned long long*)&ws[k][tx * 4];
            unsigned long long wp1 = *(const unsigned long long*)&ws[k][tx * 4 + 2];
            #pragma unroll
            for (int m = 0; m < 4; m++) {
                unsigned long long xp = *(const unsigned long long*)&xd[ty * 4 + m][k];
                asm("fma.rn.f32x2 %0, %1, %2, %0;" : "+l"(accp[m][0]) : "l"(xp), "l"(wp0));
                asm("fma.rn.f32x2 %0, %1, %2, %0;" : "+l"(accp[m][1]) : "l"(xp), "l"(wp1));
            }
        }
        __syncthreads();
    }

    // unpack accumulators
    float4 hv[4];
    #pragma unroll
    for (int m = 0; m < 4; m++) {
        float2 lo = *(float2*)&accp[m][0];
        float2 hi = *(float2*)&accp[m][1];
        hv[m] = make_float4(lo.x, lo.y, hi.x, hi.y);
    }

    // store h
    #pragma unroll
    for (int m = 0; m < 4; m++) {
        int row = bm + ty * 4 + m;
        *(float4*)&g_h[(long long)row * DD + tx * 4] = hv[m];
    }

    // s1 / s2 (block owns full rows) -> direct stores
    const int c = tx * 4;
    float4 a1 = *(const float4*)&a[c];
    float4 a2 = *(const float4*)&a[DD + c];
    #pragma unroll
    for (int m = 0; m < 4; m++) {
        float p1 = hv[m].x * a1.x + hv[m].y * a1.y + hv[m].z * a1.z + hv[m].w * a1.w;
        float p2 = hv[m].x * a2.x + hv[m].y * a2.y + hv[m].z * a2.z + hv[m].w * a2.w;
        #pragma unroll
        for (int o = 16; o > 0; o >>= 1) {
            p1 += __shfl_xor_sync(0xffffffffu, p1, o);
            p2 += __shfl_xor_sync(0xffffffffu, p2, o);
        }
        if (tx == 0) {
            int row = bm + ty * 4 + m;
            g_s1[row] = p1;
            g_s2[row] = p2;
        }
    }

    // partial column sums over this block's 32 rows (shc aliases xd: mainloop done)
    float* shc = (float*)xd;
    if (threadIdx.x < DD) shc[threadIdx.x] = 0.0f;
    __syncthreads();
    float4 cs = make_float4(0.f, 0.f, 0.f, 0.f);
    #pragma unroll
    for (int m = 0; m < 4; m++) {
        cs.x += hv[m].x; cs.y += hv[m].y; cs.z += hv[m].z; cs.w += hv[m].w;
    }
    atomicAdd(&shc[c], cs.x);
    atomicAdd(&shc[c + 1], cs.y);
    atomicAdd(&shc[c + 2], cs.z);
    atomicAdd(&shc[c + 3], cs.w);
    __syncthreads();
    if (threadIdx.x < DD) g_ShPart[blockIdx.x][threadIdx.x] = shc[threadIdx.x];
}

// ---------------- fill: Sh reduction (block 0) + slotted edge scatter (blocks 1..)
//   g_cnt is zero on entry (static init on first call; k_out re-zeroes each call)
#define FILL_U 4
#define FILL_EBLK (256 * FILL_U)
__global__ void k_fill(const void* __restrict__ ei) {
    if (blockIdx.x == 0) {
        // reduce g_ShPart -> g_Sh   (threads 0..127, each sums 512 partials)
        if (threadIdx.x < DD) {
            float s = 0.0f;
            #pragma unroll 8
            for (int b = 0; b < NBLK_GEMM; b++) s += g_ShPart[b][threadIdx.x];
            g_Sh[threadIdx.x] = s;
        }
        return;
    }

    // per-block dtype detect: int64-LE with values<2^31 -> odd 32-bit words zero
    __shared__ int s_is64;
    if (threadIdx.x == 0) {
        const int* p = (const int*)ei;
        int z = 0;
        #pragma unroll
        for (int i = 0; i < 16; i++) z += (p[2 * i + 1] == 0);
        s_is64 = (z == 16);
    }
    __syncthreads();
    const bool is64 = (s_is64 != 0);

    const int base = (blockIdx.x - 1) * FILL_EBLK + threadIdx.x;
    int rr[FILL_U], cc[FILL_U];
    if (is64) {
        const long long* p = (const long long*)ei;
        #pragma unroll
        for (int u = 0; u < FILL_U; u++) {
            int e = base + u * 256;
            rr[u] = (int)p[e];
            cc[u] = (int)p[(long long)EE + e];
        }
    } else {
        const int* p = (const int*)ei;
        #pragma unroll
        for (int u = 0; u < FILL_U; u++) {
            int e = base + u * 256;
            rr[u] = p[e];
            cc[u] = p[EE + e];
        }
    }
    #pragma unroll
    for (int u = 0; u < FILL_U; u++) {
        int slot = atomicAdd(&g_cnt[rr[u]], 1);
        if (slot < ROWCAP) g_cols[rr[u] * ROWCAP + slot] = cc[u];
    }
}

// ---------------- out: warp per row, in-row dedup, gather h[col], combine.
//   Also re-zeroes g_cnt[row] for the next graph replay.
__global__ void k_out(float* __restrict__ out) {
    __shared__ int   sc[8][ROWCAP];
    __shared__ float sw[8][ROWCAP];

    const int warp = threadIdx.x >> 5;
    const int lane = threadIdx.x & 31;
    const int row = blockIdx.x * 8 + warp;

    int cnt = g_cnt[row];
    if (cnt > ROWCAP) cnt = ROWCAP;          // statistically unreachable clamp
    const int base = row * ROWCAP;
    const float s1i = g_s1[row];

    // load row's column list into shared
    for (int j = lane; j < cnt; j += 32) sc[warp][j] = g_cols[base + j];
    __syncwarp();

    // reset counter for next call (after read)
    if (lane == 0) g_cnt[row] = 0;

    // weights with in-row dedup (duplicate (r,c) must count once, matching .set)
    for (int j = lane; j < cnt; j += 32) {
        int c = sc[warp][j];
        bool dup = false;
        for (int t = 0; t < j; t++)
            if (sc[warp][t] == c) { dup = true; break; }
        float w = 0.0f;
        if (!dup) {
            float e = s1i + __ldg(&g_s2[c]);
            e = (e > 0.0f) ? e : 0.2f * e;       // LeakyReLU(0.2)
            w = __expf(e) - 1.0f;                // exp(e) - exp(0)
        }
        sw[warp][j] = w;
    }
    __syncwarp();

    float4 acc = make_float4(0.f, 0.f, 0.f, 0.f);
    float wsum = 0.0f;

    // 4-way unrolled gather: issue four float4 loads before consuming any,
    // maximizing MLP on the L2-latency-bound neighbor gather.
    int t = 0;
    for (; t + 4 <= cnt; t += 4) {
        const int   c0 = sc[warp][t],     c1 = sc[warp][t + 1];
        const int   c2 = sc[warp][t + 2], c3 = sc[warp][t + 3];
        const float w0 = sw[warp][t],     w1 = sw[warp][t + 1];
        const float w2 = sw[warp][t + 2], w3 = sw[warp][t + 3];
        const float4 hv0 = ((const float4*)g_h)[(long long)c0 * 32 + lane];
        const float4 hv1 = ((const float4*)g_h)[(long long)c1 * 32 + lane];
        const float4 hv2 = ((const float4*)g_h)[(long long)c2 * 32 + lane];
        const float4 hv3 = ((const float4*)g_h)[(long long)c3 * 32 + lane];
        acc.x += w0 * hv0.x; acc.y += w0 * hv0.y; acc.z += w0 * hv0.z; acc.w += w0 * hv0.w; wsum += w0;
        acc.x += w1 * hv1.x; acc.y += w1 * hv1.y; acc.z += w1 * hv1.z; acc.w += w1 * hv1.w; wsum += w1;
        acc.x += w2 * hv2.x; acc.y += w2 * hv2.y; acc.z += w2 * hv2.z; acc.w += w2 * hv2.w; wsum += w2;
        acc.x += w3 * hv3.x; acc.y += w3 * hv3.y; acc.z += w3 * hv3.z; acc.w += w3 * hv3.w; wsum += w3;
    }
    for (; t < cnt; t++) {
        const int   c0 = sc[warp][t];
        const float w0 = sw[warp][t];
        const float4 hv0 = ((const float4*)g_h)[(long long)c0 * 32 + lane];
        acc.x += w0 * hv0.x; acc.y += w0 * hv0.y; acc.z += w0 * hv0.z; acc.w += w0 * hv0.w;
        wsum += w0;
    }

    const float4 sh = ((const float4*)g_Sh)[lane];
    const float inv = 1.0f / ((float)NN + wsum);
    float4 o;
    o.x = (sh.x + acc.x) * inv;
    o.y = (sh.y + acc.y) * inv;
    o.z = (sh.z + acc.z) * inv;
    o.w = (sh.w + acc.w) * inv;
    ((float4*)out)[(long long)row * 32 + lane] = o;
}

// ---------------- launcher: 3 graph nodes ----------------
extern "C" void kernel_launch(void* const* d_in, const int* in_sizes, int n_in,
                              void* d_out, int out_size) {
    const float* x  = (const float*)d_in[0];   // [16384,128] f32
    const void*  ei = d_in[1];                 // [2,524288] int64 (or int32 — detected)
    const float* W  = (const float*)d_in[2];   // [128,128] f32
    const float* a  = (const float*)d_in[3];   // [256] f32
    float* out = (float*)d_out;                // [16384,128] f32

    k_gemm<<<NBLK_GEMM, 256>>>(x, W, a);
    k_fill<<<1 + EE / FILL_EBLK, 256>>>(ei);
    k_out<<<NN / 8, 256>>>(out);
}

// round 7
// speedup vs baseline: 1.3157x; 1.3157x over previous
#include <cuda_runtime.h>
#include <cuda_bf16.h>
#include <cstdint>

// Problem constants (fixed by the dataset problem)
#define NN   16384          // nodes
#define DD   128            // feature dim (in == out)
#define EE   524288         // edges
#define ROWCAP 192          // per-row slot cap (max expected degree ~57; Binomial(E,1/N))
#define NBLK_GEMM (NN / 64) // 256

// ---------------- device scratch (no allocations allowed) ----------------
__device__ float g_h[NN * DD];                 // 8 MB   h = x @ W
__device__ float g_s1[NN];
__device__ float g_s2[NN];
__device__ float g_Sh[DD];                     // total column sums (written by k_fill blk 0)
__device__ float g_ShPart[NBLK_GEMM][DD];      // per-gemm-block partial column sums
__device__ int   g_cnt[NN];                    // zero at start of every call (self-cleaning)
__device__ int   g_cols[NN * ROWCAP];          // slotted adjacency, 12.6 MB

// ---------------- GEMM: h = x @ W  (64 rows x 128 cols per block, 512 threads)
//   Same tile/instruction mix as the proven R5 kernel, but 2x the warps per CTA
//   (each thread 4 rows x 4 cols) to double occupancy: grid=256 was the limiter.
//   Epilogue: s1,s2 direct store; partial column sums -> g_ShPart.
__global__ void k_gemm(const float* __restrict__ x, const float* __restrict__ W,
                       const float* __restrict__ a) {
    __shared__ float xs[64][36];    // [m][k], padded
    __shared__ float ws[32][128];   // [k][n]
    __shared__ float shc[128];      // block column sums

    const int tx = threadIdx.x & 31;        // 0..31 -> cols tx*4 .. tx*4+3
    const int ty = threadIdx.x >> 5;        // 0..15 -> rows ty*4 .. ty*4+3
    const int bm = blockIdx.x * 64;

    float4 acc[4];
    #pragma unroll
    for (int m = 0; m < 4; m++) acc[m] = make_float4(0.f, 0.f, 0.f, 0.f);

    for (int k0 = 0; k0 < DD; k0 += 32) {
        // load x tile: 64 rows x 32 k = 512 float4, one per thread
        {
            int i = threadIdx.x;
            int r = i >> 3, c4 = i & 7;
            float4 v = ((const float4*)x)[(long long)(bm + r) * (DD / 4) + (k0 >> 2) + c4];
            *(float4*)&xs[r][c4 * 4] = v;
        }
        // load W tile: 32 k x 128 n = 1024 float4, two per thread
        #pragma unroll
        for (int i = 0; i < 2; i++) {
            int idx = threadIdx.x + i * 512;
            int kk = idx >> 5, n4 = idx & 31;
            float4 v = ((const float4*)W)[(long long)(k0 + kk) * (DD / 4) + n4];
            *(float4*)&ws[kk][n4 * 4] = v;
        }
        __syncthreads();

        #pragma unroll
        for (int k = 0; k < 32; k++) {
            float4 wv = *(const float4*)&ws[k][tx * 4];
            #pragma unroll
            for (int m = 0; m < 4; m++) {
                float xv = xs[ty * 4 + m][k];
                acc[m].x += xv * wv.x;
                acc[m].y += xv * wv.y;
                acc[m].z += xv * wv.z;
                acc[m].w += xv * wv.w;
            }
        }
        __syncthreads();
    }

    // store h
    #pragma unroll
    for (int m = 0; m < 4; m++) {
        long long row = bm + ty * 4 + m;
        *(float4*)&g_h[row * DD + tx * 4] = acc[m];
    }

    // s1 / s2 (each warp owns full 128-col rows) -> direct stores
    const int c = tx * 4;
    float4 a1 = *(const float4*)&a[c];
    float4 a2 = *(const float4*)&a[DD + c];
    #pragma unroll
    for (int m = 0; m < 4; m++) {
        float p1 = acc[m].x * a1.x + acc[m].y * a1.y + acc[m].z * a1.z + acc[m].w * a1.w;
        float p2 = acc[m].x * a2.x + acc[m].y * a2.y + acc[m].z * a2.z + acc[m].w * a2.w;
        #pragma unroll
        for (int o = 16; o > 0; o >>= 1) {
            p1 += __shfl_xor_sync(0xffffffffu, p1, o);
            p2 += __shfl_xor_sync(0xffffffffu, p2, o);
        }
        if (tx == 0) {
            int row = bm + ty * 4 + m;
            g_s1[row] = p1;
            g_s2[row] = p2;
        }
    }

    // partial column sums over this block's 64 rows
    if (threadIdx.x < 128) shc[threadIdx.x] = 0.0f;
    __syncthreads();
    float4 cs = make_float4(0.f, 0.f, 0.f, 0.f);
    #pragma unroll
    for (int m = 0; m < 4; m++) {
        cs.x += acc[m].x; cs.y += acc[m].y; cs.z += acc[m].z; cs.w += acc[m].w;
    }
    atomicAdd(&shc[c], cs.x);
    atomicAdd(&shc[c + 1], cs.y);
    atomicAdd(&shc[c + 2], cs.z);
    atomicAdd(&shc[c + 3], cs.w);
    __syncthreads();
    if (threadIdx.x < 128) g_ShPart[blockIdx.x][threadIdx.x] = shc[threadIdx.x];
}

// ---------------- fill: Sh reduction (block 0) + slotted edge scatter (blocks 1..)
//   g_cnt is zero on entry (static init on first call; k_out re-zeroes each call)
#define FILL_U 4
#define FILL_EBLK (256 * FILL_U)
__global__ void k_fill(const void* __restrict__ ei) {
    if (blockIdx.x == 0) {
        // reduce g_ShPart -> g_Sh   (threads 0..127, each sums 256 partials)
        if (threadIdx.x < DD) {
            float s = 0.0f;
            #pragma unroll 8
            for (int b = 0; b < NBLK_GEMM; b++) s += g_ShPart[b][threadIdx.x];
            g_Sh[threadIdx.x] = s;
        }
        return;
    }

    // per-block dtype detect: int64-LE with values<2^31 -> odd 32-bit words zero
    __shared__ int s_is64;
    if (threadIdx.x == 0) {
        const int* p = (const int*)ei;
        int z = 0;
        #pragma unroll
        for (int i = 0; i < 16; i++) z += (p[2 * i + 1] == 0);
        s_is64 = (z == 16);
    }
    __syncthreads();
    const bool is64 = (s_is64 != 0);

    const int base = (blockIdx.x - 1) * FILL_EBLK + threadIdx.x;
    int rr[FILL_U], cc[FILL_U];
    if (is64) {
        const long long* p = (const long long*)ei;
        #pragma unroll
        for (int u = 0; u < FILL_U; u++) {
            int e = base + u * 256;
            rr[u] = (int)p[e];
            cc[u] = (int)p[(long long)EE + e];
        }
    } else {
        const int* p = (const int*)ei;
        #pragma unroll
        for (int u = 0; u < FILL_U; u++) {
            int e = base + u * 256;
            rr[u] = p[e];
            cc[u] = p[EE + e];
        }
    }
    #pragma unroll
    for (int u = 0; u < FILL_U; u++) {
        int slot = atomicAdd(&g_cnt[rr[u]], 1);
        if (slot < ROWCAP) g_cols[rr[u] * ROWCAP + slot] = cc[u];
    }
}

// ---------------- out: warp per row, in-row dedup, gather h[col], combine.
//   Also re-zeroes g_cnt[row] for the next graph replay. (Exact R5 version.)
__global__ void k_out(float* __restrict__ out) {
    __shared__ int   sc[8][ROWCAP];
    __shared__ float sw[8][ROWCAP];

    const int warp = threadIdx.x >> 5;
    const int lane = threadIdx.x & 31;
    const int row = blockIdx.x * 8 + warp;

    int cnt = g_cnt[row];
    if (cnt > ROWCAP) cnt = ROWCAP;          // statistically unreachable clamp
    const int base = row * ROWCAP;
    const float s1i = g_s1[row];

    // load row's column list into shared
    for (int j = lane; j < cnt; j += 32) sc[warp][j] = g_cols[base + j];
    __syncwarp();

    // reset counter for next call (after read)
    if (lane == 0) g_cnt[row] = 0;

    // weights with in-row dedup (duplicate (r,c) must count once, matching .set)
    for (int j = lane; j < cnt; j += 32) {
        int c = sc[warp][j];
        bool dup = false;
        for (int t = 0; t < j; t++)
            if (sc[warp][t] == c) { dup = true; break; }
        float w = 0.0f;
        if (!dup) {
            float e = s1i + __ldg(&g_s2[c]);
            e = (e > 0.0f) ? e : 0.2f * e;       // LeakyReLU(0.2)
            w = __expf(e) - 1.0f;                // exp(e) - exp(0)
        }
        sw[warp][j] = w;
    }
    __syncwarp();

    float4 acc = make_float4(0.f, 0.f, 0.f, 0.f);
    float wsum = 0.0f;

    // 2-way unrolled gather (proven in the 77.5us measurement)
    int t = 0;
    for (; t + 2 <= cnt; t += 2) {
        const int   c0 = sc[warp][t];
        const int   c1 = sc[warp][t + 1];
        const float w0 = sw[warp][t];
        const float w1 = sw[warp][t + 1];
        const float4 hv0 = ((const float4*)g_h)[(long long)c0 * 32 + lane];
        const float4 hv1 = ((const float4*)g_h)[(long long)c1 * 32 + lane];
        acc.x += w0 * hv0.x; acc.y += w0 * hv0.y;
        acc.z += w0 * hv0.z; acc.w += w0 * hv0.w;
        wsum += w0;
        acc.x += w1 * hv1.x; acc.y += w1 * hv1.y;
        acc.z += w1 * hv1.z; acc.w += w1 * hv1.w;
        wsum += w1;
    }
    if (t < cnt) {
        const int   c0 = sc[warp][t];
        const float w0 = sw[warp][t];
        const float4 hv0 = ((const float4*)g_h)[(long long)c0 * 32 + lane];
        acc.x += w0 * hv0.x; acc.y += w0 * hv0.y;
        acc.z += w0 * hv0.z; acc.w += w0 * hv0.w;
        wsum += w0;
    }

    const float4 sh = ((const float4*)g_Sh)[lane];
    const float inv = 1.0f / ((float)NN + wsum);
    float4 o;
    o.x = (sh.x + acc.x) * inv;
    o.y = (sh.y + acc.y) * inv;
    o.z = (sh.z + acc.z) * inv;
    o.w = (sh.w + acc.w) * inv;
    ((float4*)out)[(long long)row * 32 + lane] = o;
}

// ---------------- launcher: 3 graph nodes ----------------
extern "C" void kernel_launch(void* const* d_in, const int* in_sizes, int n_in,
                              void* d_out, int out_size) {
    const float* x  = (const float*)d_in[0];   // [16384,128] f32
    const void*  ei = d_in[1];                 // [2,524288] int64 (or int32 — detected)
    const float* W  = (const float*)d_in[2];   // [128,128] f32
    const float* a  = (const float*)d_in[3];   // [256] f32
    float* out = (float*)d_out;                // [16384,128] f32

    k_gemm<<<NBLK_GEMM, 512>>>(x, W, a);
    k_fill<<<1 + EE / FILL_EBLK, 256>>>(ei);
    k_out<<<NN / 8, 256>>>(out);
}

// round 8
// speedup vs baseline: 1.4316x; 1.0881x over previous
#include <cuda_runtime.h>
#include <cuda_bf16.h>
#include <cstdint>

// Problem constants (fixed by the dataset problem)
#define NN   16384          // nodes
#define DD   128            // feature dim (in == out)
#define EE   524288         // edges
#define ROWCAP 192          // per-row slot cap (max expected degree ~57; Binomial(E,1/N))
#define NBLK_GEMM (NN / 64) // 256
#define FILL_U 4
#define FILL_THREADS 512
#define FILL_EBLK (FILL_THREADS * FILL_U)          // 2048 edges/block
#define NBLK_FILL (EE / FILL_EBLK)                 // 256

// ---------------- device scratch (no allocations allowed) ----------------
__device__ float g_h[NN * DD];                 // 8 MB   h = x @ W
__device__ float g_s1[NN];
__device__ float g_s2[NN];
__device__ float g_Sh[DD];                     // total column sums
__device__ float g_ShPart[NBLK_GEMM][DD];      // per-gemm-block partial column sums
__device__ int   g_done;                       // gemm-block completion counter (self-reset)
__device__ int   g_cnt[NN];                    // zero at start of every call (self-cleaning)
__device__ int   g_cols[NN * ROWCAP];          // slotted adjacency, 12.6 MB

// ---------------- fused kernel: blocks [0,256) gemm, blocks [256,512) edge fill
//   gemm: 64 rows x 128 cols per block, 512 threads, 4x4 per thread (R7-measured).
//   Last gemm block to finish reduces ShPart -> Sh (fence+counter, self-cleaning).
//   fill: slotted CSR scatter; independent of gemm, overlaps with it.
__global__ void k_main(const float* __restrict__ x, const float* __restrict__ W,
                       const float* __restrict__ a, const void* __restrict__ ei) {
    __shared__ float xs[64][36];    // [m][k], padded          (gemm branch)
    __shared__ float ws[32][128];   // [k][n]                  (gemm branch)
    __shared__ float shc[128];      // block column sums       (gemm branch)
    __shared__ float red[4][128];   // ShPart reduction        (last gemm block)
    __shared__ int   s_flag;        // is64 (fill) / last-block (gemm)

    if (blockIdx.x >= NBLK_GEMM) {
        // ---------------- fill branch ----------------
        // per-block dtype detect: int64-LE with values<2^31 -> odd 32-bit words zero
        if (threadIdx.x == 0) {
            const int* p = (const int*)ei;
            int z = 0;
            #pragma unroll
            for (int i = 0; i < 16; i++) z += (p[2 * i + 1] == 0);
            s_flag = (z == 16);
        }
        __syncthreads();
        const bool is64 = (s_flag != 0);

        const int base = (blockIdx.x - NBLK_GEMM) * FILL_EBLK + threadIdx.x;
        int rr[FILL_U], cc[FILL_U];
        if (is64) {
            const long long* p = (const long long*)ei;
            #pragma unroll
            for (int u = 0; u < FILL_U; u++) {
                int e = base + u * FILL_THREADS;
                rr[u] = (int)p[e];
                cc[u] = (int)p[(long long)EE + e];
            }
        } else {
            const int* p = (const int*)ei;
            #pragma unroll
            for (int u = 0; u < FILL_U; u++) {
                int e = base + u * FILL_THREADS;
                rr[u] = p[e];
                cc[u] = p[EE + e];
            }
        }
        #pragma unroll
        for (int u = 0; u < FILL_U; u++) {
            int slot = atomicAdd(&g_cnt[rr[u]], 1);
            if (slot < ROWCAP) g_cols[rr[u] * ROWCAP + slot] = cc[u];
        }
        return;
    }

    // ---------------- gemm branch (identical math to the 77.5us kernel) ----------------
    const int tx = threadIdx.x & 31;        // 0..31 -> cols tx*4 .. tx*4+3
    const int ty = threadIdx.x >> 5;        // 0..15 -> rows ty*4 .. ty*4+3
    const int bm = blockIdx.x * 64;

    float4 acc[4];
    #pragma unroll
    for (int m = 0; m < 4; m++) acc[m] = make_float4(0.f, 0.f, 0.f, 0.f);

    for (int k0 = 0; k0 < DD; k0 += 32) {
        {   // x tile: 64 rows x 32 k = 512 float4, one per thread
            int i = threadIdx.x;
            int r = i >> 3, c4 = i & 7;
            float4 v = ((const float4*)x)[(long long)(bm + r) * (DD / 4) + (k0 >> 2) + c4];
            *(float4*)&xs[r][c4 * 4] = v;
        }
        #pragma unroll
        for (int i = 0; i < 2; i++) {   // W tile: 32 k x 128 n = 1024 float4
            int idx = threadIdx.x + i * 512;
            int kk = idx >> 5, n4 = idx & 31;
            float4 v = ((const float4*)W)[(long long)(k0 + kk) * (DD / 4) + n4];
            *(float4*)&ws[kk][n4 * 4] = v;
        }
        __syncthreads();

        #pragma unroll
        for (int k = 0; k < 32; k++) {
            float4 wv = *(const float4*)&ws[k][tx * 4];
            #pragma unroll
            for (int m = 0; m < 4; m++) {
                float xv = xs[ty * 4 + m][k];
                acc[m].x += xv * wv.x;
                acc[m].y += xv * wv.y;
                acc[m].z += xv * wv.z;
                acc[m].w += xv * wv.w;
            }
        }
        __syncthreads();
    }

    // store h
    #pragma unroll
    for (int m = 0; m < 4; m++) {
        long long row = bm + ty * 4 + m;
        *(float4*)&g_h[row * DD + tx * 4] = acc[m];
    }

    // s1 / s2 (each warp owns full 128-col rows) -> direct stores
    const int c = tx * 4;
    float4 a1 = *(const float4*)&a[c];
    float4 a2 = *(const float4*)&a[DD + c];
    #pragma unroll
    for (int m = 0; m < 4; m++) {
        float p1 = acc[m].x * a1.x + acc[m].y * a1.y + acc[m].z * a1.z + acc[m].w * a1.w;
        float p2 = acc[m].x * a2.x + acc[m].y * a2.y + acc[m].z * a2.z + acc[m].w * a2.w;
        #pragma unroll
        for (int o = 16; o > 0; o >>= 1) {
            p1 += __shfl_xor_sync(0xffffffffu, p1, o);
            p2 += __shfl_xor_sync(0xffffffffu, p2, o);
        }
        if (tx == 0) {
            int row = bm + ty * 4 + m;
            g_s1[row] = p1;
            g_s2[row] = p2;
        }
    }

    // partial column sums over this block's 64 rows
    if (threadIdx.x < 128) shc[threadIdx.x] = 0.0f;
    __syncthreads();
    float4 cs = make_float4(0.f, 0.f, 0.f, 0.f);
    #pragma unroll
    for (int m = 0; m < 4; m++) {
        cs.x += acc[m].x; cs.y += acc[m].y; cs.z += acc[m].z; cs.w += acc[m].w;
    }
    atomicAdd(&shc[c], cs.x);
    atomicAdd(&shc[c + 1], cs.y);
    atomicAdd(&shc[c + 2], cs.z);
    atomicAdd(&shc[c + 3], cs.w);
    __syncthreads();
    if (threadIdx.x < 128) g_ShPart[blockIdx.x][threadIdx.x] = shc[threadIdx.x];

    // last-gemm-block-done reduces ShPart -> Sh (fence+counter, deterministic)
    __threadfence();
    if (threadIdx.x == 0)
        s_flag = (atomicAdd(&g_done, 1) == NBLK_GEMM - 1);
    __syncthreads();
    if (s_flag) {
        __threadfence();                        // acquire: see all ShPart writes
        const int col  = threadIdx.x & 127;
        const int part = threadIdx.x >> 7;      // 0..3, each sums 64 blocks
        float s = 0.0f;
        #pragma unroll 8
        for (int b = part * 64; b < part * 64 + 64; b++) s += g_ShPart[b][col];
        red[part][col] = s;
        __syncthreads();
        if (threadIdx.x < 128)
            g_Sh[threadIdx.x] = red[0][threadIdx.x] + red[1][threadIdx.x]
                              + red[2][threadIdx.x] + red[3][threadIdx.x];
        if (threadIdx.x == 0) g_done = 0;       // self-clean for next replay
    }
}

// ---------------- out: warp per row, in-row dedup, gather h[col], combine.
//   Also re-zeroes g_cnt[row] for the next graph replay. (Exact R5/R7 version.)
__global__ void k_out(float* __restrict__ out) {
    __shared__ int   sc[8][ROWCAP];
    __shared__ float sw[8][ROWCAP];

    const int warp = threadIdx.x >> 5;
    const int lane = threadIdx.x & 31;
    const int row = blockIdx.x * 8 + warp;

    int cnt = g_cnt[row];
    if (cnt > ROWCAP) cnt = ROWCAP;          // statistically unreachable clamp
    const int base = row * ROWCAP;
    const float s1i = g_s1[row];

    for (int j = lane; j < cnt; j += 32) sc[warp][j] = g_cols[base + j];
    __syncwarp();

    if (lane == 0) g_cnt[row] = 0;           // reset counter for next call

    for (int j = lane; j < cnt; j += 32) {
        int c = sc[warp][j];
        bool dup = false;
        for (int t = 0; t < j; t++)
            if (sc[warp][t] == c) { dup = true; break; }
        float w = 0.0f;
        if (!dup) {
            float e = s1i + __ldg(&g_s2[c]);
            e = (e > 0.0f) ? e : 0.2f * e;       // LeakyReLU(0.2)
            w = __expf(e) - 1.0f;                // exp(e) - exp(0)
        }
        sw[warp][j] = w;
    }
    __syncwarp();

    float4 acc = make_float4(0.f, 0.f, 0.f, 0.f);
    float wsum = 0.0f;

    int t = 0;
    for (; t + 2 <= cnt; t += 2) {
        const int   c0 = sc[warp][t];
        const int   c1 = sc[warp][t + 1];
        const float w0 = sw[warp][t];
        const float w1 = sw[warp][t + 1];
        const float4 hv0 = ((const float4*)g_h)[(long long)c0 * 32 + lane];
        const float4 hv1 = ((const float4*)g_h)[(long long)c1 * 32 + lane];
        acc.x += w0 * hv0.x; acc.y += w0 * hv0.y;
        acc.z += w0 * hv0.z; acc.w += w0 * hv0.w;
        wsum += w0;
        acc.x += w1 * hv1.x; acc.y += w1 * hv1.y;
        acc.z += w1 * hv1.z; acc.w += w1 * hv1.w;
        wsum += w1;
    }
    if (t < cnt) {
        const int   c0 = sc[warp][t];
        const float w0 = sw[warp][t];
        const float4 hv0 = ((const float4*)g_h)[(long long)c0 * 32 + lane];
        acc.x += w0 * hv0.x; acc.y += w0 * hv0.y;
        acc.z += w0 * hv0.z; acc.w += w0 * hv0.w;
        wsum += w0;
    }

    const float4 sh = ((const float4*)g_Sh)[lane];
    const float inv = 1.0f / ((float)NN + wsum);
    float4 o;
    o.x = (sh.x + acc.x) * inv;
    o.y = (sh.y + acc.y) * inv;
    o.z = (sh.z + acc.z) * inv;
    o.w = (sh.w + acc.w) * inv;
    ((float4*)out)[(long long)row * 32 + lane] = o;
}

// ---------------- launcher: 2 graph nodes ----------------
extern "C" void kernel_launch(void* const* d_in, const int* in_sizes, int n_in,
                              void* d_out, int out_size) {
    const float* x  = (const float*)d_in[0];   // [16384,128] f32
    const void*  ei = d_in[1];                 // [2,524288] int64 (or int32 — detected)
    const float* W  = (const float*)d_in[2];   // [128,128] f32
    const float* a  = (const float*)d_in[3];   // [256] f32
    float* out = (float*)d_out;                // [16384,128] f32

    k_main<<<NBLK_GEMM + NBLK_FILL, 512>>>(x, W, a, ei);
    k_out<<<NN / 8, 256>>>(out);
}

// round 9
// speedup vs baseline: 1.8198x; 1.2712x over previous
#include <cuda_runtime.h>
#include <cuda_bf16.h>
#include <cstdint>

// Problem constants (fixed by the dataset problem)
#define NN   16384          // nodes
#define DD   128            // feature dim (in == out)
#define EE   524288         // edges
#define ROWCAP 192          // per-row slot cap (max expected degree ~57; Binomial(E,1/N))
#define NBLK_GEMM (NN / 64) // 256
#define FILL_U 4
#define FILL_THREADS 512
#define FILL_EBLK (FILL_THREADS * FILL_U)          // 2048 edges/block
#define NBLK_FILL (EE / FILL_EBLK)                 // 256

// ---------------- device scratch (no allocations allowed) ----------------
__device__ float g_h[NN * DD];                 // 8 MB   h = x @ W
__device__ float g_s1[NN];
__device__ float g_s2[NN];
__device__ float g_Sh[DD];                     // total column sums
__device__ float g_ShPart[NBLK_GEMM][DD];      // per-gemm-block partial column sums
__device__ int   g_done;                       // gemm-block completion counter (self-reset)
__device__ int   g_cnt[NN];                    // zero at start of every call (self-cleaning)
__device__ int   g_cols[NN * ROWCAP];          // slotted adjacency, 12.6 MB

// ---------------- fused kernel: blocks [0,256) gemm, blocks [256,512) edge fill
//   gemm: 64 rows x 128 cols per block, 512 threads, 4x4 per thread (R7/R8-measured).
//   Last gemm block to finish reduces ShPart -> Sh (fence+counter, self-cleaning).
//   fill: slotted CSR scatter; independent of gemm, overlaps with it.
__global__ void k_main(const float* __restrict__ x, const float* __restrict__ W,
                       const float* __restrict__ a, const void* __restrict__ ei) {
    __shared__ float xs[64][36];    // [m][k], padded          (gemm branch)
    __shared__ float ws[32][128];   // [k][n]                  (gemm branch)
    __shared__ float shc[128];      // block column sums       (gemm branch)
    __shared__ float red[4][128];   // ShPart reduction        (last gemm block)
    __shared__ int   s_flag;        // is64 (fill) / last-block (gemm)

    if (blockIdx.x >= NBLK_GEMM) {
        // ---------------- fill branch ----------------
        // per-block dtype detect: int64-LE with values<2^31 -> odd 32-bit words zero
        if (threadIdx.x == 0) {
            const int* p = (const int*)ei;
            int z = 0;
            #pragma unroll
            for (int i = 0; i < 16; i++) z += (p[2 * i + 1] == 0);
            s_flag = (z == 16);
        }
        __syncthreads();
        const bool is64 = (s_flag != 0);

        const int base = (blockIdx.x - NBLK_GEMM) * FILL_EBLK + threadIdx.x;
        int rr[FILL_U], cc[FILL_U];
        if (is64) {
            const long long* p = (const long long*)ei;
            #pragma unroll
            for (int u = 0; u < FILL_U; u++) {
                int e = base + u * FILL_THREADS;
                rr[u] = (int)p[e];
                cc[u] = (int)p[(long long)EE + e];
            }
        } else {
            const int* p = (const int*)ei;
            #pragma unroll
            for (int u = 0; u < FILL_U; u++) {
                int e = base + u * FILL_THREADS;
                rr[u] = p[e];
                cc[u] = p[EE + e];
            }
        }
        #pragma unroll
        for (int u = 0; u < FILL_U; u++) {
            int slot = atomicAdd(&g_cnt[rr[u]], 1);
            if (slot < ROWCAP) g_cols[rr[u] * ROWCAP + slot] = cc[u];
        }
        return;
    }

    // ---------------- gemm branch (identical math to the 71.6us kernel) ----------------
    const int tx = threadIdx.x & 31;        // 0..31 -> cols tx*4 .. tx*4+3
    const int ty = threadIdx.x >> 5;        // 0..15 -> rows ty*4 .. ty*4+3
    const int bm = blockIdx.x * 64;

    float4 acc[4];
    #pragma unroll
    for (int m = 0; m < 4; m++) acc[m] = make_float4(0.f, 0.f, 0.f, 0.f);

    for (int k0 = 0; k0 < DD; k0 += 32) {
        {   // x tile: 64 rows x 32 k = 512 float4, one per thread
            int i = threadIdx.x;
            int r = i >> 3, c4 = i & 7;
            float4 v = ((const float4*)x)[(long long)(bm + r) * (DD / 4) + (k0 >> 2) + c4];
            *(float4*)&xs[r][c4 * 4] = v;
        }
        #pragma unroll
        for (int i = 0; i < 2; i++) {   // W tile: 32 k x 128 n = 1024 float4
            int idx = threadIdx.x + i * 512;
            int kk = idx >> 5, n4 = idx & 31;
            float4 v = ((const float4*)W)[(long long)(k0 + kk) * (DD / 4) + n4];
            *(float4*)&ws[kk][n4 * 4] = v;
        }
        __syncthreads();

        #pragma unroll
        for (int k = 0; k < 32; k++) {
            float4 wv = *(const float4*)&ws[k][tx * 4];
            #pragma unroll
            for (int m = 0; m < 4; m++) {
                float xv = xs[ty * 4 + m][k];
                acc[m].x += xv * wv.x;
                acc[m].y += xv * wv.y;
                acc[m].z += xv * wv.z;
                acc[m].w += xv * wv.w;
            }
        }
        __syncthreads();
    }

    // store h
    #pragma unroll
    for (int m = 0; m < 4; m++) {
        long long row = bm + ty * 4 + m;
        *(float4*)&g_h[row * DD + tx * 4] = acc[m];
    }

    // s1 / s2 (each warp owns full 128-col rows) -> direct stores
    const int c = tx * 4;
    float4 a1 = *(const float4*)&a[c];
    float4 a2 = *(const float4*)&a[DD + c];
    #pragma unroll
    for (int m = 0; m < 4; m++) {
        float p1 = acc[m].x * a1.x + acc[m].y * a1.y + acc[m].z * a1.z + acc[m].w * a1.w;
        float p2 = acc[m].x * a2.x + acc[m].y * a2.y + acc[m].z * a2.z + acc[m].w * a2.w;
        #pragma unroll
        for (int o = 16; o > 0; o >>= 1) {
            p1 += __shfl_xor_sync(0xffffffffu, p1, o);
            p2 += __shfl_xor_sync(0xffffffffu, p2, o);
        }
        if (tx == 0) {
            int row = bm + ty * 4 + m;
            g_s1[row] = p1;
            g_s2[row] = p2;
        }
    }

    // partial column sums over this block's 64 rows
    if (threadIdx.x < 128) shc[threadIdx.x] = 0.0f;
    __syncthreads();
    float4 cs = make_float4(0.f, 0.f, 0.f, 0.f);
    #pragma unroll
    for (int m = 0; m < 4; m++) {
        cs.x += acc[m].x; cs.y += acc[m].y; cs.z += acc[m].z; cs.w += acc[m].w;
    }
    atomicAdd(&shc[c], cs.x);
    atomicAdd(&shc[c + 1], cs.y);
    atomicAdd(&shc[c + 2], cs.z);
    atomicAdd(&shc[c + 3], cs.w);
    __syncthreads();
    if (threadIdx.x < 128) g_ShPart[blockIdx.x][threadIdx.x] = shc[threadIdx.x];

    // last-gemm-block-done reduces ShPart -> Sh (fence+counter, deterministic)
    __threadfence();
    if (threadIdx.x == 0)
        s_flag = (atomicAdd(&g_done, 1) == NBLK_GEMM - 1);
    __syncthreads();
    if (s_flag) {
        __threadfence();                        // acquire: see all ShPart writes
        const int col  = threadIdx.x & 127;
        const int part = threadIdx.x >> 7;      // 0..3, each sums 64 blocks
        float s = 0.0f;
        #pragma unroll 8
        for (int b = part * 64; b < part * 64 + 64; b++) s += g_ShPart[b][col];
        red[part][col] = s;
        __syncthreads();
        if (threadIdx.x < 128)
            g_Sh[threadIdx.x] = red[0][threadIdx.x] + red[1][threadIdx.x]
                              + red[2][threadIdx.x] + red[3][threadIdx.x];
        if (threadIdx.x == 0) g_done = 0;       // self-clean for next replay
    }
}

// ---------------- out: warp per row; O(1) bitmap dedup in shared; int32 gather
//   indexing; 4-way unrolled L2 gather. Re-zeroes g_cnt[row] for next replay.
__global__ void k_out(float* __restrict__ out) {
    __shared__ int      sc[8][ROWCAP];          // 6 KB
    __shared__ float    sw[8][ROWCAP];          // 6 KB
    __shared__ unsigned bmp[8][NN / 32];        // 16 KB: per-warp 16384-bit bitmap

    const int warp = threadIdx.x >> 5;
    const int lane = threadIdx.x & 31;
    const int row = blockIdx.x * 8 + warp;

    // clear this warp's bitmap: 512 words = 128 uint4, 4 per lane
    {
        uint4* bv = (uint4*)bmp[warp];
        uint4 z = make_uint4(0u, 0u, 0u, 0u);
        #pragma unroll
        for (int i = 0; i < 4; i++) bv[lane + i * 32] = z;
    }

    int cnt = g_cnt[row];
    if (cnt > ROWCAP) cnt = ROWCAP;          // statistically unreachable clamp
    const int base = row * ROWCAP;
    const float s1i = g_s1[row];

    for (int j = lane; j < cnt; j += 32) sc[warp][j] = g_cols[base + j];
    __syncwarp();

    if (lane == 0) g_cnt[row] = 0;           // reset counter for next call

    // weights with bitmap dedup: duplicate (r,c) keeps exactly one nonzero w.
    // (equal (r,c) -> equal w, so any atomic winner yields identical output)
    for (int j = lane; j < cnt; j += 32) {
        int c = sc[warp][j];
        unsigned bit = 1u << (c & 31);
        unsigned old = atomicOr(&bmp[warp][c >> 5], bit);
        float w = 0.0f;
        if (!(old & bit)) {
            float e = s1i + __ldg(&g_s2[c]);
            e = (e > 0.0f) ? e : 0.2f * e;       // LeakyReLU(0.2)
            w = __expf(e) - 1.0f;                // exp(e) - exp(0)
        }
        sw[warp][j] = w;
    }
    __syncwarp();

    const float4* hb = (const float4*)g_h;
    float4 acc = make_float4(0.f, 0.f, 0.f, 0.f);
    float wsum = 0.0f;

    // 4-way unrolled gather, all-int32 indexing (c*32+lane < 2^20)
    int t = 0;
    for (; t + 4 <= cnt; t += 4) {
        const int   c0 = sc[warp][t],     c1 = sc[warp][t + 1];
        const int   c2 = sc[warp][t + 2], c3 = sc[warp][t + 3];
        const float w0 = sw[warp][t],     w1 = sw[warp][t + 1];
        const float w2 = sw[warp][t + 2], w3 = sw[warp][t + 3];
        const float4 hv0 = hb[c0 * 32 + lane];
        const float4 hv1 = hb[c1 * 32 + lane];
        const float4 hv2 = hb[c2 * 32 + lane];
        const float4 hv3 = hb[c3 * 32 + lane];
        acc.x += w0 * hv0.x; acc.y += w0 * hv0.y; acc.z += w0 * hv0.z; acc.w += w0 * hv0.w; wsum += w0;
        acc.x += w1 * hv1.x; acc.y += w1 * hv1.y; acc.z += w1 * hv1.z; acc.w += w1 * hv1.w; wsum += w1;
        acc.x += w2 * hv2.x; acc.y += w2 * hv2.y; acc.z += w2 * hv2.z; acc.w += w2 * hv2.w; wsum += w2;
        acc.x += w3 * hv3.x; acc.y += w3 * hv3.y; acc.z += w3 * hv3.z; acc.w += w3 * hv3.w; wsum += w3;
    }
    for (; t < cnt; t++) {
        const int   c0 = sc[warp][t];
        const float w0 = sw[warp][t];
        const float4 hv0 = hb[c0 * 32 + lane];
        acc.x += w0 * hv0.x; acc.y += w0 * hv0.y; acc.z += w0 * hv0.z; acc.w += w0 * hv0.w;
        wsum += w0;
    }

    const float4 sh = ((const float4*)g_Sh)[lane];
    const float inv = 1.0f / ((float)NN + wsum);
    float4 o;
    o.x = (sh.x + acc.x) * inv;
    o.y = (sh.y + acc.y) * inv;
    o.z = (sh.z + acc.z) * inv;
    o.w = (sh.w + acc.w) * inv;
    ((float4*)out)[row * 32 + lane] = o;
}

// ---------------- launcher: 2 graph nodes ----------------
extern "C" void kernel_launch(void* const* d_in, const int* in_sizes, int n_in,
                              void* d_out, int out_size) {
    const float* x  = (const float*)d_in[0];   // [16384,128] f32
    const void*  ei = d_in[1];                 // [2,524288] int64 (or int32 — detected)
    const float* W  = (const float*)d_in[2];   // [128,128] f32
    const float* a  = (const float*)d_in[3];   // [256] f32
    float* out = (float*)d_out;                // [16384,128] f32

    k_main<<<NBLK_GEMM + NBLK_FILL, 512>>>(x, W, a, ei);
    k_out<<<NN / 8, 256>>>(out);
}